// round 14
// baseline (speedup 1.0000x reference)
#include <cuda_runtime.h>
#include <cuda_bf16.h>
#include <cstdint>

// CustomContrastiveLoss on GB300 (sm_103 plain-target tensor path).
// loss = mean_i sum_{j: ad[i]==ad[j], valid} min( logsum_i - t_ij , -log2(1e-12) )
// t_ij = log2(e) * dot(logits_i, labels_j); logsum_i = log2( sum_j 2^(t_ij) )
// bf16 1-term: t ~= bf16(a*log2e) . bf16(b).  Fixed-offset softmax: C=64.
// Flash GEMM runs as a persistent kernel (296 CTAs = 2/SM) pulling
// (rowtile, octant) tasks from an atomic queue -> even per-SM tensor load.

#define LOG2E  1.4426950408889634f
#define CAPV   39.863137138648354f   // -log2(1e-12)
#define CEXP   64.0f                 // fixed softmax offset
#define NMAX   8192
#define DDIM   128
#define NIDS   1000
#define NCHUNK 8                     // 8 chunks of 1024 rows
#define FXSCALE 1048576.0f           // 2^20 fixed point
#define NPART  16                    // pz slots per row: 8 octants x 2 warpgroups

// ---------------- scratch (static __device__; no allocations) ----------------
__device__ __nv_bfloat16 g_Ah[(size_t)NMAX * 128];   // bf16(logits * log2e)
__device__ __nv_bfloat16 g_Bh[(size_t)NMAX * 128];   // bf16(labels)
__device__ float g_maskf[NMAX];                      // -64 valid / -1e30 invalid
__device__ float g_pz[NPART * NMAX];                 // partial row sum 2^(t-64)
__device__ int   g_ad[NMAX];
__device__ int   g_cnt[8192];                        // (id, chunk) counts; zero at load,
                                                     // re-zeroed by matched_kernel each call
__device__ int   g_boff[8192];                       // exclusive prefix of g_cnt
__device__ int   g_bucket[NMAX];                     // row indices grouped by id
__device__ unsigned long long g_fx;                  // fixed-point loss accumulator
__device__ unsigned int g_done;                      // finalize ticket
__device__ unsigned int g_task;                      // flash task queue head

// ---------------- helpers ----------------
__device__ __forceinline__ float fexp2(float x) {
    float y; asm("ex2.approx.ftz.f32 %0, %1;" : "=f"(y) : "f"(x)); return y;
}
__device__ __forceinline__ float flog2(float x) {
    float y; asm("lg2.approx.f32 %0, %1;" : "=f"(y) : "f"(x)); return y;
}
__device__ __forceinline__ uint32_t smem_u32(const void* p) {
    uint32_t a;
    asm("{ .reg .u64 t; cvta.to.shared.u64 t, %1; cvt.u32.u64 %0, t; }" : "=r"(a) : "l"(p));
    return a;
}
__device__ __forceinline__ uint32_t swz(uint32_t x) { return x ^ ((x >> 3) & 0x70u); }

__device__ __forceinline__ void cp_async16(uint32_t saddr, const void* gptr) {
    asm volatile("cp.async.cg.shared.global [%0], [%1], 16;"
                 :: "r"(saddr), "l"(__cvta_generic_to_global(gptr)) : "memory");
}
#define CP_COMMIT() asm volatile("cp.async.commit_group;" ::: "memory")
#define CP_WAIT0()  asm volatile("cp.async.wait_group 0;" ::: "memory")

__device__ __forceinline__ void ldsm4(uint32_t& r0, uint32_t& r1, uint32_t& r2,
                                      uint32_t& r3, uint32_t a) {
    asm volatile("ldmatrix.sync.aligned.m8n8.x4.shared.b16 {%0,%1,%2,%3}, [%4];"
                 : "=r"(r0), "=r"(r1), "=r"(r2), "=r"(r3) : "r"(a));
}
__device__ __forceinline__ void mma16816(float* c, const uint32_t* a, const uint32_t* b) {
    asm volatile("mma.sync.aligned.m16n8k16.row.col.f32.bf16.bf16.f32 "
                 "{%0,%1,%2,%3}, {%4,%5,%6,%7}, {%8,%9}, {%0,%1,%2,%3};"
                 : "+f"(c[0]), "+f"(c[1]), "+f"(c[2]), "+f"(c[3])
                 : "r"(a[0]), "r"(a[1]), "r"(a[2]), "r"(a[3]), "r"(b[0]), "r"(b[1]));
}

// ---------------- smem layout for flash (dynamic) ----------------
#define SM_B     0                     // 2 x 32768  (B tile double buffer)
#define SM_MASK  65536                 // 2 x 512
#define SM_A     66560                 // 2 x 16384  (A tile, K=128)
#define SM_TOTAL (SM_A + 32768)        // 99328 B  -> 2 CTAs/SM

// ---------------------------------------------------------------------------
// merged prep (4 floats/thread, grid 1024 — the proven round-12 shape):
// bf16 quantize (A pre-scaled by log2e), ad/mask fold, histogram (atomic
// counts order-independent -> deterministic), accumulator + task-queue reset.
// int64-vs-int32 detection: per-warp ballot on the first 32 odd words.
// ---------------------------------------------------------------------------
__global__ void prep_all_kernel(const float* __restrict__ logits,
                                const float* __restrict__ labels,
                                const int* __restrict__ pad,
                                const void* __restrict__ ad, int n) {
    const int gid = blockIdx.x * 256 + threadIdx.x;

    if (gid == 0) { g_fx = 0ULL; g_done = 0u; g_task = 0u; }

    const int lane = threadIdx.x & 31;
    const int nz = (((const int*)ad)[2 * lane + 1] != 0);
    const int is64 = (__ballot_sync(0xffffffffu, nz) == 0u);

    if (gid < (n * DDIM) / 4) {
        float4 la = reinterpret_cast<const float4*>(logits)[gid];
        float4 lb = reinterpret_cast<const float4*>(labels)[gid];
        __nv_bfloat162* pa = reinterpret_cast<__nv_bfloat162*>(g_Ah) + gid * 2;
        __nv_bfloat162* pb = reinterpret_cast<__nv_bfloat162*>(g_Bh) + gid * 2;
        pa[0] = __floats2bfloat162_rn(la.x * LOG2E, la.y * LOG2E);
        pa[1] = __floats2bfloat162_rn(la.z * LOG2E, la.w * LOG2E);
        pb[0] = __floats2bfloat162_rn(lb.x, lb.y);
        pb[1] = __floats2bfloat162_rn(lb.z, lb.w);
    }
    if (gid < n) {
        int v;
        if (is64) v = (int)((const long long*)ad)[gid];
        else      v = ((const int*)ad)[gid];
        const bool ok = pad[gid] != 0;
        g_ad[gid]    = ok ? v : -(gid + 2);
        g_maskf[gid] = ok ? -CEXP : -1.0e30f;
        if (ok) atomicAdd(&g_cnt[v * NCHUNK + (gid >> 10)], 1);
    }
}

// ---------------------------------------------------------------------------
// scatter body (runs as extra blocks of the flash launch, 256 threads):
// thread t owns ids 4t..4t+3 = g_cnt[32t..32t+32) -> bucket offsets stay in
// registers after a reg+shuffle exclusive scan. One 1024-row chunk per block,
// ascending row order (deterministic). Scatter-block 0 publishes g_boff.
// ---------------------------------------------------------------------------
__device__ void scatter_body(char* smem, int n, int blk) {
    int* s_ad = reinterpret_cast<int*>(smem);          // 1024 ints
    int* s_w  = reinterpret_cast<int*>(smem) + 1024;   // 8 ints
    const int t = threadIdx.x, lane = t & 31, wid = t >> 5;

    int v[32], run = 0;
#pragma unroll
    for (int q = 0; q < 32; q++) { v[q] = run; run += g_cnt[t * 32 + q]; }
    int inc = run;
#pragma unroll
    for (int o = 1; o < 32; o <<= 1) {
        int u = __shfl_up_sync(0xffffffffu, inc, o);
        if (lane >= o) inc += u;
    }
    if (lane == 31) s_w[wid] = inc;                    // 8 warp totals

    const int c0 = blk << 10;
#pragma unroll
    for (int q = 0; q < 4; q++) {
        int r = t * 4 + q;
        s_ad[r] = (c0 + r < n) ? g_ad[c0 + r] : -1;
    }
    __syncthreads();
    if (wid == 0 && lane < 8) {
        int w = s_w[lane];
#pragma unroll
        for (int o = 1; o < 8; o <<= 1) {
            int u = __shfl_up_sync(0x000000ffu, w, o);
            if (lane >= o) w += u;
        }
        s_w[lane] = w;
    }
    __syncthreads();
    const int base = (wid ? s_w[wid - 1] : 0) + (inc - run);

    if (blk == 0) {
#pragma unroll
        for (int q = 0; q < 32; q++) g_boff[t * 32 + q] = base + v[q];
    }

    int p0 = base + v[0 * NCHUNK + blk];
    int p1 = base + v[1 * NCHUNK + blk];
    int p2 = base + v[2 * NCHUNK + blk];
    int p3 = base + v[3 * NCHUNK + blk];
    for (int r = 0; r < 1024; r++) {
        int a = s_ad[r];
        if (a >= 0 && (a >> 2) == t) {
            int q = a & 3;
            int pos = (q == 0) ? p0++ : (q == 1) ? p1++ : (q == 2) ? p2++ : p3++;
            g_bucket[pos] = c0 + r;
        }
    }
}

// ---------------------------------------------------------------------------
// Flash kernel (persistent): blocks [0, nFlash) are workers that pop
// (rowtile, octant) tasks; blocks >= nFlash run the scatter path.
// Task = 128 rows x 1024 cols = 8 col-tiles of 128, K=128 bf16,
// double-buffered B. z += 2^(t - 64) (mask carries the -64 offset).
// pz slot = octant*2 + warpgroup -> deterministic regardless of scheduling.
// ---------------------------------------------------------------------------
__global__ __launch_bounds__(256, 2)
void flash_kernel(int n, int nFlash) {
    extern __shared__ char smem[];
    if ((int)blockIdx.x >= nFlash) {
        scatter_body(smem, n, (int)blockIdx.x - nFlash);
        return;
    }
    __shared__ int s_task;
    const uint32_t sbase = smem_u32(smem);
    const int tid  = threadIdx.x;
    const int wid  = tid >> 5;
    const int lane = tid & 31;
    const int warpRow = (wid & 3) * 32;
    const int warpCol = (wid >> 2) * 64;

    const int nRow   = n >> 7;            // 64 rowtiles
    const int nTasks = nRow * 8;          // 512 tasks
    const int colsPT = n >> 3;            // 1024 cols per task
    const int NT     = colsPT >> 7;       // 8 col tiles per task

    const uint32_t aRow = (uint32_t)(warpRow + (lane & 15)) * 128u;
    const uint32_t aXor = (uint32_t)((lane & 15) & 7) << 4;
    const uint32_t aKl  = (uint32_t)(lane >> 4) * 16u;
    const int      jB   = (lane & 7) + ((lane >> 4) << 3);
    const uint32_t bRow = (uint32_t)(warpCol + jB) * 128u;
    const uint32_t bXor = (uint32_t)(lane & 7) << 4;
    const uint32_t bKl  = (uint32_t)((lane >> 3) & 1) * 16u;

    for (;;) {
        if (tid == 0) s_task = (int)atomicAdd(&g_task, 1u);
        __syncthreads();
        const int task = s_task;
        if (task >= nTasks) break;
        const int row0  = (task >> 3) * 128;
        const int oct   = task & 7;
        const int col0b = oct * colsPT;

        // ---- prologue: A tile (32 KB), B tile0 (32 KB), mask0 — one group
#pragma unroll
        for (int i = 0; i < 8; i++) {
            int v = tid + 256 * i;
            int ch = v >> 10, w = v & 1023;
            int r = w >> 3, g8 = w & 7;
            cp_async16(sbase + SM_A + ch * 16384 + swz((uint32_t)(r * 128 + g8 * 16)),
                       &g_Ah[(size_t)(row0 + r) * 128 + ch * 64 + g8 * 8]);
        }
#pragma unroll
        for (int i = 0; i < 8; i++) {
            int v = tid + 256 * i;
            int ch = v >> 10, w = v & 1023;
            int r = w >> 3, g8 = w & 7;
            cp_async16(sbase + SM_B + ch * 16384 + swz((uint32_t)(r * 128 + g8 * 16)),
                       &g_Bh[(size_t)(col0b + r) * 128 + ch * 64 + g8 * 8]);
        }
        if (tid < 32)
            cp_async16(sbase + SM_MASK + tid * 16, &g_maskf[col0b + tid * 4]);
        CP_COMMIT();

        float acc[2][8][4];
#pragma unroll
        for (int mt = 0; mt < 2; mt++)
#pragma unroll
            for (int nt = 0; nt < 8; nt++)
#pragma unroll
                for (int e = 0; e < 4; e++) acc[mt][nt][e] = 0.0f;

        float zrun[4] = {0.0f, 0.0f, 0.0f, 0.0f};

        for (int t = 0; t < NT; t++) {
            const int buf = t & 1;
            CP_WAIT0();
            __syncthreads();

            if (t + 1 < NT) {
                int j0 = col0b + (t + 1) * 128;
                uint32_t sb = sbase + SM_B + (buf ^ 1) * 32768;
#pragma unroll
                for (int i = 0; i < 8; i++) {
                    int v = tid + 256 * i;
                    int ch = v >> 10, w = v & 1023;
                    int r = w >> 3, g8 = w & 7;
                    cp_async16(sb + ch * 16384 + swz((uint32_t)(r * 128 + g8 * 16)),
                               &g_Bh[(size_t)(j0 + r) * 128 + ch * 64 + g8 * 8]);
                }
                if (tid < 32)
                    cp_async16(sbase + SM_MASK + (buf ^ 1) * 512 + tid * 16,
                               &g_maskf[j0 + tid * 4]);
            }
            CP_COMMIT();

            const uint32_t bBB = sbase + SM_B + (uint32_t)buf * 32768u;
#pragma unroll
            for (int ks = 0; ks < 8; ks++) {
                const uint32_t ch = (uint32_t)(ks >> 2);
                const uint32_t kk = (uint32_t)(ks & 3) * 32u;
                const uint32_t kOffA = (kk + aKl) ^ aXor;
                const uint32_t kOffB = (kk + bKl) ^ bXor;
                uint32_t a0[4], a1[4];
                const uint32_t aCB = sbase + SM_A + ch * 16384u;
                ldsm4(a0[0], a0[1], a0[2], a0[3], aCB + aRow + kOffA);
                ldsm4(a1[0], a1[1], a1[2], a1[3], aCB + 2048u + aRow + kOffA);
                uint32_t b[8][2];
                const uint32_t bCB = bBB + ch * 16384u;
#pragma unroll
                for (int p = 0; p < 4; p++)
                    ldsm4(b[2 * p][0], b[2 * p][1], b[2 * p + 1][0], b[2 * p + 1][1],
                          bCB + bRow + (uint32_t)p * 2048u + kOffB);
#pragma unroll
                for (int nt = 0; nt < 8; nt++) {
                    mma16816(acc[0][nt], a0, b[nt]);
                    mma16816(acc[1][nt], a1, b[nt]);
                }
            }

            {
                const float* mk = (const float*)(smem + SM_MASK + buf * 512)
                                  + warpCol + (lane & 3) * 2;
#pragma unroll
                for (int mt = 0; mt < 2; mt++)
#pragma unroll
                    for (int rp = 0; rp < 2; rp++) {
                        float zs = 0.0f;
#pragma unroll
                        for (int nt = 0; nt < 8; nt++) {
                            float2 mv = *(const float2*)(mk + nt * 8);
                            zs += fexp2(acc[mt][nt][rp * 2 + 0] + mv.x);
                            zs += fexp2(acc[mt][nt][rp * 2 + 1] + mv.y);
                        }
                        zrun[mt * 2 + rp] += zs;
                    }
#pragma unroll
                for (int mt = 0; mt < 2; mt++)
#pragma unroll
                    for (int nt = 0; nt < 8; nt++)
#pragma unroll
                        for (int e = 0; e < 4; e++) acc[mt][nt][e] = 0.0f;
            }
        }

        // write this task's pz slot
#pragma unroll
        for (int s = 0; s < 4; s++) {
            float z = zrun[s];
            z += __shfl_xor_sync(0xffffffffu, z, 1);
            z += __shfl_xor_sync(0xffffffffu, z, 2);
            if ((lane & 3) == 0) {
                int mt = s >> 1, rp = s & 1;
                int row = row0 + warpRow + mt * 16 + rp * 8 + (lane >> 2);
                int slot = oct * 2 + (wid >> 2);
                g_pz[slot * NMAX + row] = z;
            }
        }
        __syncthreads();      // protect smem before next task's prologue
    }
}

// ---------------------------------------------------------------------------
// matched: one warp per row; lane = one float4 of the dot; bucket loop with
// software-pipelined b-row loads; 16-lane parallel z-slot sum. Block 0
// re-zeroes g_cnt for the next graph replay. Row losses accumulate into a
// fixed-point u64 (order-independent -> deterministic); last block writes
// the mean.
// ---------------------------------------------------------------------------
__global__ __launch_bounds__(256)
void matched_kernel(const float* __restrict__ logits,
                    const float* __restrict__ labels,
                    float* __restrict__ out, int n, int nblocks) {
    if (blockIdx.x == 0) {
        for (int i = threadIdx.x; i < 8192; i += 256) g_cnt[i] = 0;
    }

    const int warp = threadIdx.x >> 5;
    const int lane = threadIdx.x & 31;
    const int row  = blockIdx.x * 8 + warp;

    if (row < n) {                     // warp-uniform
        const int id = g_ad[row];
        if (id >= 0) {                 // warp-uniform
            // 16 lanes load the 16 z-slots in parallel, 4-shuffle sum
            float zp = (lane < NPART) ? g_pz[lane * NMAX + row] : 0.0f;
            zp += __shfl_xor_sync(0xffffffffu, zp, 1);
            zp += __shfl_xor_sync(0xffffffffu, zp, 2);
            zp += __shfl_xor_sync(0xffffffffu, zp, 4);
            zp += __shfl_xor_sync(0xffffffffu, zp, 8);
            const float lz = flog2(__shfl_sync(0xffffffffu, zp, 0)) + CEXP;

            const float4 a4 = reinterpret_cast<const float4*>(logits + (size_t)row * DDIM)[lane];
            const int s = g_boff[id * NCHUNK];
            const int e = g_boff[(id + 1) * NCHUNK];

            // software pipeline: b row for entry p+1 loads during reduce of p
            float acc = 0.0f;
            int j = g_bucket[s];       // bucket non-empty: contains `row` itself
            float4 b = reinterpret_cast<const float4*>(labels + (size_t)j * DDIM)[lane];
            for (int p = s; p < e; p++) {     // uniform across warp
                const float4 bc = b;
                if (p + 1 < e) {              // warp-uniform branch
                    const int j2 = g_bucket[p + 1];
                    b = reinterpret_cast<const float4*>(labels + (size_t)j2 * DDIM)[lane];
                }
                float d = a4.x * bc.x + a4.y * bc.y + a4.z * bc.z + a4.w * bc.w;
#pragma unroll
                for (int o = 16; o; o >>= 1) d += __shfl_xor_sync(0xffffffffu, d, o);
                acc += fminf(lz - d * LOG2E, CAPV);
            }
            if (lane == 0 && acc != 0.0f)
                atomicAdd(&g_fx, (unsigned long long)llrintf(acc * FXSCALE));
        }
    }

    // finalize: last block to arrive writes the mean
    __syncthreads();
    if (threadIdx.x == 0) {
        __threadfence();
        unsigned t = atomicAdd(&g_done, 1u);
        if (t == (unsigned)(nblocks - 1)) {
            unsigned long long fx = atomicAdd(&g_fx, 0ULL);
            out[0] = (float)((double)fx / (double)FXSCALE / (double)n);
        }
    }
}

// ---------------------------------------------------------------------------
extern "C" void kernel_launch(void* const* d_in, const int* in_sizes, int n_in,
                              void* d_out, int out_size) {
    const float* logits = (const float*)d_in[0];
    const float* labels = (const float*)d_in[1];
    const int*   pad    = (const int*)d_in[2];
    const void*  ad     = d_in[3];
    float*       out    = (float*)d_out;
    const int n = in_sizes[2];           // B*S = 8192

    // g_cnt is zeroed at module load and re-zeroed by matched_kernel each call.
    prep_all_kernel<<<(n * DDIM / 4 + 255) / 256, 256>>>(logits, labels, pad, ad, n);

    const int nFlash = 296;              // 2 persistent CTAs per SM (148 SMs)
    cudaFuncSetAttribute(flash_kernel,
                         cudaFuncAttributeMaxDynamicSharedMemorySize, SM_TOTAL);
    flash_kernel<<<nFlash + NCHUNK, 256, SM_TOTAL>>>(n, nFlash);

    const int nblocks = (n + 7) / 8;
    matched_kernel<<<nblocks, 256>>>(logits, labels, out, n, nblocks);
}

// round 16
// speedup vs baseline: 1.1015x; 1.1015x over previous
#include <cuda_runtime.h>
#include <cuda_bf16.h>
#include <cstdint>

// CustomContrastiveLoss on GB300 (sm_103 plain-target tensor path).
// loss = mean_i sum_{j: ad[i]==ad[j], valid} min( logsum_i - t_ij , -log2(1e-12) )
// t_ij = log2(e) * dot(logits_i, labels_j); logsum_i = log2( sum_j 2^(t_ij) )
// bf16 1-term: t ~= bf16(a*log2e) . bf16(b).  Fixed-offset softmax: C=64.

#define LOG2E  1.4426950408889634f
#define CAPV   39.863137138648354f   // -log2(1e-12)
#define CEXP   64.0f                 // fixed softmax offset
#define NMAX   8192
#define DDIM   128
#define NIDS   1000
#define NCHUNK 8                     // 8 chunks of 1024 rows
#define FXSCALE 1048576.0f           // 2^20 fixed point

// ---------------- scratch (static __device__; no allocations) ----------------
__device__ __nv_bfloat16 g_Ah[(size_t)NMAX * 128];   // bf16(logits * log2e)
__device__ __nv_bfloat16 g_Bh[(size_t)NMAX * 128];   // bf16(labels)
__device__ float g_maskf[NMAX];                      // -64 valid / -1e30 invalid
__device__ float g_pz[8 * NMAX];                     // partial row sum 2^(t-64), 8 slots
__device__ int   g_ad[NMAX];
__device__ int   g_cnt[8192];                        // (id, chunk) counts; zero at load,
                                                     // re-zeroed by matched_kernel each call
__device__ int   g_boff[8192];                       // exclusive prefix of g_cnt
__device__ int   g_bucket[NMAX];                     // row indices grouped by id
__device__ unsigned long long g_fx;                  // fixed-point loss accumulator
__device__ unsigned int g_done;                      // finalize ticket

// ---------------- helpers ----------------
__device__ __forceinline__ float fexp2(float x) {
    float y; asm("ex2.approx.ftz.f32 %0, %1;" : "=f"(y) : "f"(x)); return y;
}
__device__ __forceinline__ float flog2(float x) {
    float y; asm("lg2.approx.f32 %0, %1;" : "=f"(y) : "f"(x)); return y;
}
__device__ __forceinline__ uint32_t smem_u32(const void* p) {
    uint32_t a;
    asm("{ .reg .u64 t; cvta.to.shared.u64 t, %1; cvt.u32.u64 %0, t; }" : "=r"(a) : "l"(p));
    return a;
}
__device__ __forceinline__ uint32_t swz(uint32_t x) { return x ^ ((x >> 3) & 0x70u); }

__device__ __forceinline__ void cp_async16(uint32_t saddr, const void* gptr) {
    asm volatile("cp.async.cg.shared.global [%0], [%1], 16;"
                 :: "r"(saddr), "l"(__cvta_generic_to_global(gptr)) : "memory");
}
#define CP_COMMIT() asm volatile("cp.async.commit_group;" ::: "memory")
#define CP_WAIT0()  asm volatile("cp.async.wait_group 0;" ::: "memory")

__device__ __forceinline__ void ldsm4(uint32_t& r0, uint32_t& r1, uint32_t& r2,
                                      uint32_t& r3, uint32_t a) {
    asm volatile("ldmatrix.sync.aligned.m8n8.x4.shared.b16 {%0,%1,%2,%3}, [%4];"
                 : "=r"(r0), "=r"(r1), "=r"(r2), "=r"(r3) : "r"(a));
}
__device__ __forceinline__ void mma16816(float* c, const uint32_t* a, const uint32_t* b) {
    asm volatile("mma.sync.aligned.m16n8k16.row.col.f32.bf16.bf16.f32 "
                 "{%0,%1,%2,%3}, {%4,%5,%6,%7}, {%8,%9}, {%0,%1,%2,%3};"
                 : "+f"(c[0]), "+f"(c[1]), "+f"(c[2]), "+f"(c[3])
                 : "r"(a[0]), "r"(a[1]), "r"(a[2]), "r"(a[3]), "r"(b[0]), "r"(b[1]));
}

// ---------------- smem layout for flash (dynamic) ----------------
#define SM_B     0                     // 2 x 32768  (B tile double buffer)
#define SM_MASK  65536                 // 2 x 512
#define SM_A     66560                 // 2 x 16384  (A resident, K=128)
#define SM_TOTAL (SM_A + 32768)        // 99328 B  -> 2 CTAs/SM

// ---------------------------------------------------------------------------
// merged prep (4 floats/thread, grid 1024 — measured-best shape): bf16
// quantize (A pre-scaled by log2e), ad/mask fold, histogram (atomic counts
// order-independent -> deterministic), accumulator zeroing. int64-vs-int32
// detection: per-warp ballot on the first 32 odd words (all zero => int64).
// ---------------------------------------------------------------------------
__global__ void prep_all_kernel(const float* __restrict__ logits,
                                const float* __restrict__ labels,
                                const int* __restrict__ pad,
                                const void* __restrict__ ad, int n) {
    const int gid = blockIdx.x * 256 + threadIdx.x;

    if (gid == 0) { g_fx = 0ULL; g_done = 0u; }

    const int lane = threadIdx.x & 31;
    const int nz = (((const int*)ad)[2 * lane + 1] != 0);
    const int is64 = (__ballot_sync(0xffffffffu, nz) == 0u);

    if (gid < (n * DDIM) / 4) {
        float4 la = reinterpret_cast<const float4*>(logits)[gid];
        float4 lb = reinterpret_cast<const float4*>(labels)[gid];
        __nv_bfloat162* pa = reinterpret_cast<__nv_bfloat162*>(g_Ah) + gid * 2;
        __nv_bfloat162* pb = reinterpret_cast<__nv_bfloat162*>(g_Bh) + gid * 2;
        pa[0] = __floats2bfloat162_rn(la.x * LOG2E, la.y * LOG2E);
        pa[1] = __floats2bfloat162_rn(la.z * LOG2E, la.w * LOG2E);
        pb[0] = __floats2bfloat162_rn(lb.x, lb.y);
        pb[1] = __floats2bfloat162_rn(lb.z, lb.w);
    }
    if (gid < n) {
        int v;
        if (is64) v = (int)((const long long*)ad)[gid];
        else      v = ((const int*)ad)[gid];
        const bool ok = pad[gid] != 0;
        g_ad[gid]    = ok ? v : -(gid + 2);
        g_maskf[gid] = ok ? -CEXP : -1.0e30f;
        if (ok) atomicAdd(&g_cnt[v * NCHUNK + (gid >> 10)], 1);
    }
}

// ---------------------------------------------------------------------------
// scatter body (runs as extra blocks of the flash launch, 256 threads):
// thread t owns ids 4t..4t+3 = g_cnt[32t..32t+32) -> bucket offsets stay in
// registers after a reg+shuffle exclusive scan. One 1024-row chunk per block,
// ascending row order (deterministic). Scatter-block 0 publishes g_boff.
// ---------------------------------------------------------------------------
__device__ void scatter_body(char* smem, int n, int blk) {
    int* s_ad = reinterpret_cast<int*>(smem);          // 1024 ints
    int* s_w  = reinterpret_cast<int*>(smem) + 1024;   // 8 ints
    const int t = threadIdx.x, lane = t & 31, wid = t >> 5;

    int v[32], run = 0;
#pragma unroll
    for (int q = 0; q < 32; q++) { v[q] = run; run += g_cnt[t * 32 + q]; }
    int inc = run;
#pragma unroll
    for (int o = 1; o < 32; o <<= 1) {
        int u = __shfl_up_sync(0xffffffffu, inc, o);
        if (lane >= o) inc += u;
    }
    if (lane == 31) s_w[wid] = inc;                    // 8 warp totals

    const int c0 = blk << 10;
#pragma unroll
    for (int q = 0; q < 4; q++) {
        int r = t * 4 + q;
        s_ad[r] = (c0 + r < n) ? g_ad[c0 + r] : -1;
    }
    __syncthreads();
    if (wid == 0 && lane < 8) {
        int w = s_w[lane];
#pragma unroll
        for (int o = 1; o < 8; o <<= 1) {
            int u = __shfl_up_sync(0x000000ffu, w, o);
            if (lane >= o) w += u;
        }
        s_w[lane] = w;
    }
    __syncthreads();
    const int base = (wid ? s_w[wid - 1] : 0) + (inc - run);

    if (blk == 0) {
#pragma unroll
        for (int q = 0; q < 32; q++) g_boff[t * 32 + q] = base + v[q];
    }

    int p0 = base + v[0 * NCHUNK + blk];
    int p1 = base + v[1 * NCHUNK + blk];
    int p2 = base + v[2 * NCHUNK + blk];
    int p3 = base + v[3 * NCHUNK + blk];
    for (int r = 0; r < 1024; r++) {
        int a = s_ad[r];
        if (a >= 0 && (a >> 2) == t) {
            int q = a & 3;
            int pos = (q == 0) ? p0++ : (q == 1) ? p1++ : (q == 2) ? p2++ : p3++;
            g_bucket[pos] = c0 + r;
        }
    }
}

// ---------------------------------------------------------------------------
// Flash kernel (R12 static config — the measured-best): blocks [0, nFlash) =
// 64 rowtiles x 4 col-quarters (2 CTA/SM); blocks [nFlash, nFlash+8) run the
// scatter path on the underfilled SMs. Block tile 128x128 sim, K=128 bf16,
// double-buffered B tiles. No online max: z += 2^(t - 64).
// ---------------------------------------------------------------------------
__global__ __launch_bounds__(256, 2)
void flash_kernel(int n, int nFlash) {
    extern __shared__ char smem[];
    if ((int)blockIdx.x >= nFlash) {
        scatter_body(smem, n, (int)blockIdx.x - nFlash);
        return;
    }
    const uint32_t sbase = smem_u32(smem);
    const int tid  = threadIdx.x;
    const int wid  = tid >> 5;
    const int lane = tid & 31;
    const int warpRow = (wid & 3) * 32;
    const int warpCol = (wid >> 2) * 64;

    const int rt    = (int)blockIdx.x >> 2;
    const int quart = (int)blockIdx.x & 3;
    const int row0  = rt * 128;
    const int col0b = quart * (n >> 2);
    const int NT    = (n >> 2) >> 7;        // 16 col tiles of 128

    {
#pragma unroll
        for (int i = 0; i < 8; i++) {
            int v = tid + 256 * i;
            int ch = v >> 10, w = v & 1023;
            int r = w >> 3, g8 = w & 7;
            cp_async16(sbase + SM_A + ch * 16384 + swz((uint32_t)(r * 128 + g8 * 16)),
                       &g_Ah[(size_t)(row0 + r) * 128 + ch * 64 + g8 * 8]);
        }
#pragma unroll
        for (int i = 0; i < 8; i++) {
            int v = tid + 256 * i;
            int ch = v >> 10, w = v & 1023;
            int r = w >> 3, g8 = w & 7;
            cp_async16(sbase + SM_B + ch * 16384 + swz((uint32_t)(r * 128 + g8 * 16)),
                       &g_Bh[(size_t)(col0b + r) * 128 + ch * 64 + g8 * 8]);
        }
        if (tid < 32)
            cp_async16(sbase + SM_MASK + tid * 16, &g_maskf[col0b + tid * 4]);
        CP_COMMIT();
    }

    const uint32_t aRow = (uint32_t)(warpRow + (lane & 15)) * 128u;
    const uint32_t aXor = (uint32_t)((lane & 15) & 7) << 4;
    const uint32_t aKl  = (uint32_t)(lane >> 4) * 16u;
    const int      jB   = (lane & 7) + ((lane >> 4) << 3);
    const uint32_t bRow = (uint32_t)(warpCol + jB) * 128u;
    const uint32_t bXor = (uint32_t)(lane & 7) << 4;
    const uint32_t bKl  = (uint32_t)((lane >> 3) & 1) * 16u;

    float acc[2][8][4];
#pragma unroll
    for (int mt = 0; mt < 2; mt++)
#pragma unroll
        for (int nt = 0; nt < 8; nt++)
#pragma unroll
            for (int e = 0; e < 4; e++) acc[mt][nt][e] = 0.0f;

    float zrun[4] = {0.0f, 0.0f, 0.0f, 0.0f};

    for (int t = 0; t < NT; t++) {
        const int buf = t & 1;
        CP_WAIT0();
        __syncthreads();

        if (t + 1 < NT) {
            int j0 = col0b + (t + 1) * 128;
            uint32_t sb = sbase + SM_B + (buf ^ 1) * 32768;
#pragma unroll
            for (int i = 0; i < 8; i++) {
                int v = tid + 256 * i;
                int ch = v >> 10, w = v & 1023;
                int r = w >> 3, g8 = w & 7;
                cp_async16(sb + ch * 16384 + swz((uint32_t)(r * 128 + g8 * 16)),
                           &g_Bh[(size_t)(j0 + r) * 128 + ch * 64 + g8 * 8]);
            }
            if (tid < 32)
                cp_async16(sbase + SM_MASK + (buf ^ 1) * 512 + tid * 16,
                           &g_maskf[j0 + tid * 4]);
        }
        CP_COMMIT();

        const uint32_t bBB = sbase + SM_B + (uint32_t)buf * 32768u;
#pragma unroll
        for (int ks = 0; ks < 8; ks++) {
            const uint32_t ch = (uint32_t)(ks >> 2);
            const uint32_t kk = (uint32_t)(ks & 3) * 32u;
            const uint32_t kOffA = (kk + aKl) ^ aXor;
            const uint32_t kOffB = (kk + bKl) ^ bXor;
            uint32_t a0[4], a1[4];
            const uint32_t aCB = sbase + SM_A + ch * 16384u;
            ldsm4(a0[0], a0[1], a0[2], a0[3], aCB + aRow + kOffA);
            ldsm4(a1[0], a1[1], a1[2], a1[3], aCB + 2048u + aRow + kOffA);
            uint32_t b[8][2];
            const uint32_t bCB = bBB + ch * 16384u;
#pragma unroll
            for (int p = 0; p < 4; p++)
                ldsm4(b[2 * p][0], b[2 * p][1], b[2 * p + 1][0], b[2 * p + 1][1],
                      bCB + bRow + (uint32_t)p * 2048u + kOffB);
#pragma unroll
            for (int nt = 0; nt < 8; nt++) {
                mma16816(acc[0][nt], a0, b[nt]);
                mma16816(acc[1][nt], a1, b[nt]);
            }
        }

        {
            const float* mk = (const float*)(smem + SM_MASK + buf * 512)
                              + warpCol + (lane & 3) * 2;
#pragma unroll
            for (int mt = 0; mt < 2; mt++)
#pragma unroll
                for (int rp = 0; rp < 2; rp++) {
                    float zs = 0.0f;
#pragma unroll
                    for (int nt = 0; nt < 8; nt++) {
                        float2 mv = *(const float2*)(mk + nt * 8);
                        zs += fexp2(acc[mt][nt][rp * 2 + 0] + mv.x);
                        zs += fexp2(acc[mt][nt][rp * 2 + 1] + mv.y);
                    }
                    zrun[mt * 2 + rp] += zs;
                }
#pragma unroll
            for (int mt = 0; mt < 2; mt++)
#pragma unroll
                for (int nt = 0; nt < 8; nt++)
#pragma unroll
                    for (int e = 0; e < 4; e++) acc[mt][nt][e] = 0.0f;
        }
    }

#pragma unroll
    for (int s = 0; s < 4; s++) {
        float z = zrun[s];
        z += __shfl_xor_sync(0xffffffffu, z, 1);
        z += __shfl_xor_sync(0xffffffffu, z, 2);
        if ((lane & 3) == 0) {
            int mt = s >> 1, rp = s & 1;
            int row = row0 + warpRow + mt * 16 + rp * 8 + (lane >> 2);
            int slot = quart * 2 + (wid >> 2);
            g_pz[slot * NMAX + row] = z;
        }
    }
}

// ---------------------------------------------------------------------------
// matched: one warp per row; lane = one float4 of the dot; bucket loop with
// software-pipelined b-row loads (next row's load overlaps current reduce)
// and parallel 8-lane z-slot sum. Block 0 re-zeroes g_cnt for the next graph
// replay (safe: scatter has already consumed it). Row losses accumulate into
// a fixed-point u64 (order-independent -> deterministic); last block writes
// the mean.
// ---------------------------------------------------------------------------
__global__ __launch_bounds__(256)
void matched_kernel(const float* __restrict__ logits,
                    const float* __restrict__ labels,
                    float* __restrict__ out, int n, int nblocks) {
    if (blockIdx.x == 0) {
        for (int i = threadIdx.x; i < 8192; i += 256) g_cnt[i] = 0;
    }

    const int warp = threadIdx.x >> 5;
    const int lane = threadIdx.x & 31;
    const int row  = blockIdx.x * 8 + warp;

    if (row < n) {                     // warp-uniform
        const int id = g_ad[row];
        if (id >= 0) {                 // warp-uniform
            // 8 lanes load the 8 z-slots in parallel, 3-shuffle sum
            float zp = (lane < 8) ? g_pz[lane * NMAX + row] : 0.0f;
            zp += __shfl_xor_sync(0xffffffffu, zp, 1);
            zp += __shfl_xor_sync(0xffffffffu, zp, 2);
            zp += __shfl_xor_sync(0xffffffffu, zp, 4);
            const float lz = flog2(__shfl_sync(0xffffffffu, zp, 0)) + CEXP;

            const float4 a4 = reinterpret_cast<const float4*>(logits + (size_t)row * DDIM)[lane];
            const int s = g_boff[id * NCHUNK];
            const int e = g_boff[(id + 1) * NCHUNK];

            // software pipeline: b row for entry p+1 loads during reduce of p
            float acc = 0.0f;
            int j = g_bucket[s];       // bucket non-empty: contains `row` itself
            float4 b = reinterpret_cast<const float4*>(labels + (size_t)j * DDIM)[lane];
            for (int p = s; p < e; p++) {     // uniform across warp
                const float4 bc = b;
                if (p + 1 < e) {              // warp-uniform branch
                    const int j2 = g_bucket[p + 1];
                    b = reinterpret_cast<const float4*>(labels + (size_t)j2 * DDIM)[lane];
                }
                float d = a4.x * bc.x + a4.y * bc.y + a4.z * bc.z + a4.w * bc.w;
#pragma unroll
                for (int o = 16; o; o >>= 1) d += __shfl_xor_sync(0xffffffffu, d, o);
                acc += fminf(lz - d * LOG2E, CAPV);
            }
            if (lane == 0 && acc != 0.0f)
                atomicAdd(&g_fx, (unsigned long long)llrintf(acc * FXSCALE));
        }
    }

    // finalize: last block to arrive writes the mean
    __syncthreads();
    if (threadIdx.x == 0) {
        __threadfence();
        unsigned t = atomicAdd(&g_done, 1u);
        if (t == (unsigned)(nblocks - 1)) {
            unsigned long long fx = atomicAdd(&g_fx, 0ULL);
            out[0] = (float)((double)fx / (double)FXSCALE / (double)n);
        }
    }
}

// ---------------------------------------------------------------------------
extern "C" void kernel_launch(void* const* d_in, const int* in_sizes, int n_in,
                              void* d_out, int out_size) {
    const float* logits = (const float*)d_in[0];
    const float* labels = (const float*)d_in[1];
    const int*   pad    = (const int*)d_in[2];
    const void*  ad     = d_in[3];
    float*       out    = (float*)d_out;
    const int n = in_sizes[2];           // B*S = 8192

    // g_cnt is zeroed at module load and re-zeroed by matched_kernel each call.
    prep_all_kernel<<<(n * DDIM / 4 + 255) / 256, 256>>>(logits, labels, pad, ad, n);

    const int nFlash = (n / 128) * 4;    // 256
    cudaFuncSetAttribute(flash_kernel,
                         cudaFuncAttributeMaxDynamicSharedMemorySize, SM_TOTAL);
    flash_kernel<<<nFlash + NCHUNK, 256, SM_TOTAL>>>(n, nFlash);

    const int nblocks = (n + 7) / 8;
    matched_kernel<<<nblocks, 256>>>(logits, labels, out, n, nblocks);
}

// round 17
// speedup vs baseline: 1.1024x; 1.0008x over previous
#include <cuda_runtime.h>
#include <cuda_bf16.h>
#include <cstdint>

// CustomContrastiveLoss on GB300 (sm_103 plain-target tensor path).
// loss = mean_i sum_{j: ad[i]==ad[j], valid} min( logsum_i - t_ij , -log2(1e-12) )
// t_ij = log2(e) * dot(logits_i, labels_j); logsum_i = log2( sum_j 2^(t_ij) )
// bf16 1-term: t ~= bf16(a*log2e) . bf16(b).
// No softmax offset needed: t <= ~90 at 5.5 sigma over 67M pairs, and
// sum 2^t <= 2^90 * 8192 = 2^103 << 2^128 -> fp32-safe unshifted.
// Column validity as a multiplicative weight: z += 2^t * w, w in {1, 0}.

#define LOG2E  1.4426950408889634f
#define CAPV   39.863137138648354f   // -log2(1e-12)
#define NMAX   8192
#define DDIM   128
#define NIDS   1000
#define NCHUNK 8                     // 8 chunks of 1024 rows
#define FXSCALE 1048576.0f           // 2^20 fixed point

// ---------------- scratch (static __device__; no allocations) ----------------
__device__ __nv_bfloat16 g_Ah[(size_t)NMAX * 128];   // bf16(logits * log2e)
__device__ __nv_bfloat16 g_Bh[(size_t)NMAX * 128];   // bf16(labels)
__device__ float g_w[NMAX];                          // 1.0 valid / 0.0 invalid
__device__ float g_pz[8 * NMAX];                     // partial row sum 2^t, 8 slots
__device__ int   g_ad[NMAX];
__device__ int   g_cnt[8192];                        // (id, chunk) counts; zero at load,
                                                     // re-zeroed by matched_kernel each call
__device__ int   g_boff[8192];                       // exclusive prefix of g_cnt
__device__ int   g_bucket[NMAX];                     // row indices grouped by id
__device__ unsigned long long g_fx;                  // fixed-point loss accumulator
__device__ unsigned int g_done;                      // finalize ticket

// ---------------- helpers ----------------
__device__ __forceinline__ float fexp2(float x) {
    float y; asm("ex2.approx.ftz.f32 %0, %1;" : "=f"(y) : "f"(x)); return y;
}
__device__ __forceinline__ float flog2(float x) {
    float y; asm("lg2.approx.f32 %0, %1;" : "=f"(y) : "f"(x)); return y;
}
__device__ __forceinline__ uint32_t smem_u32(const void* p) {
    uint32_t a;
    asm("{ .reg .u64 t; cvta.to.shared.u64 t, %1; cvt.u32.u64 %0, t; }" : "=r"(a) : "l"(p));
    return a;
}
__device__ __forceinline__ uint32_t swz(uint32_t x) { return x ^ ((x >> 3) & 0x70u); }

__device__ __forceinline__ void cp_async16(uint32_t saddr, const void* gptr) {
    asm volatile("cp.async.cg.shared.global [%0], [%1], 16;"
                 :: "r"(saddr), "l"(__cvta_generic_to_global(gptr)) : "memory");
}
#define CP_COMMIT() asm volatile("cp.async.commit_group;" ::: "memory")
#define CP_WAIT0()  asm volatile("cp.async.wait_group 0;" ::: "memory")

__device__ __forceinline__ void ldsm4(uint32_t& r0, uint32_t& r1, uint32_t& r2,
                                      uint32_t& r3, uint32_t a) {
    asm volatile("ldmatrix.sync.aligned.m8n8.x4.shared.b16 {%0,%1,%2,%3}, [%4];"
                 : "=r"(r0), "=r"(r1), "=r"(r2), "=r"(r3) : "r"(a));
}
__device__ __forceinline__ void mma16816(float* c, const uint32_t* a, const uint32_t* b) {
    asm volatile("mma.sync.aligned.m16n8k16.row.col.f32.bf16.bf16.f32 "
                 "{%0,%1,%2,%3}, {%4,%5,%6,%7}, {%8,%9}, {%0,%1,%2,%3};"
                 : "+f"(c[0]), "+f"(c[1]), "+f"(c[2]), "+f"(c[3])
                 : "r"(a[0]), "r"(a[1]), "r"(a[2]), "r"(a[3]), "r"(b[0]), "r"(b[1]));
}

// ---------------- smem layout for flash (dynamic) ----------------
#define SM_B     0                     // 2 x 32768  (B tile double buffer)
#define SM_MASK  65536                 // 2 x 512    (column weights)
#define SM_A     66560                 // 2 x 16384  (A resident, K=128)
#define SM_TOTAL (SM_A + 32768)        // 99328 B  -> 2 CTAs/SM

// ---------------------------------------------------------------------------
// merged prep (4 floats/thread, grid 1024 — measured-best shape): bf16
// quantize (A pre-scaled by log2e), ad/weight fold, histogram (atomic counts
// order-independent -> deterministic), accumulator zeroing. int64-vs-int32
// detection: per-warp ballot on the first 32 odd words (all zero => int64).
// ---------------------------------------------------------------------------
__global__ void prep_all_kernel(const float* __restrict__ logits,
                                const float* __restrict__ labels,
                                const int* __restrict__ pad,
                                const void* __restrict__ ad, int n) {
    const int gid = blockIdx.x * 256 + threadIdx.x;

    if (gid == 0) { g_fx = 0ULL; g_done = 0u; }

    const int lane = threadIdx.x & 31;
    const int nz = (((const int*)ad)[2 * lane + 1] != 0);
    const int is64 = (__ballot_sync(0xffffffffu, nz) == 0u);

    if (gid < (n * DDIM) / 4) {
        float4 la = reinterpret_cast<const float4*>(logits)[gid];
        float4 lb = reinterpret_cast<const float4*>(labels)[gid];
        __nv_bfloat162* pa = reinterpret_cast<__nv_bfloat162*>(g_Ah) + gid * 2;
        __nv_bfloat162* pb = reinterpret_cast<__nv_bfloat162*>(g_Bh) + gid * 2;
        pa[0] = __floats2bfloat162_rn(la.x * LOG2E, la.y * LOG2E);
        pa[1] = __floats2bfloat162_rn(la.z * LOG2E, la.w * LOG2E);
        pb[0] = __floats2bfloat162_rn(lb.x, lb.y);
        pb[1] = __floats2bfloat162_rn(lb.z, lb.w);
    }
    if (gid < n) {
        int v;
        if (is64) v = (int)((const long long*)ad)[gid];
        else      v = ((const int*)ad)[gid];
        const bool ok = pad[gid] != 0;
        g_ad[gid] = ok ? v : -(gid + 2);
        g_w[gid]  = ok ? 1.0f : 0.0f;
        if (ok) atomicAdd(&g_cnt[v * NCHUNK + (gid >> 10)], 1);
    }
}

// ---------------------------------------------------------------------------
// scatter body (runs as extra blocks of the flash launch, 256 threads):
// thread t owns ids 4t..4t+3 = g_cnt[32t..32t+32) -> bucket offsets stay in
// registers after a reg+shuffle exclusive scan. One 1024-row chunk per block,
// ascending row order (deterministic). Scatter-block 0 publishes g_boff.
// ---------------------------------------------------------------------------
__device__ void scatter_body(char* smem, int n, int blk) {
    int* s_ad = reinterpret_cast<int*>(smem);          // 1024 ints
    int* s_w  = reinterpret_cast<int*>(smem) + 1024;   // 8 ints
    const int t = threadIdx.x, lane = t & 31, wid = t >> 5;

    int v[32], run = 0;
#pragma unroll
    for (int q = 0; q < 32; q++) { v[q] = run; run += g_cnt[t * 32 + q]; }
    int inc = run;
#pragma unroll
    for (int o = 1; o < 32; o <<= 1) {
        int u = __shfl_up_sync(0xffffffffu, inc, o);
        if (lane >= o) inc += u;
    }
    if (lane == 31) s_w[wid] = inc;                    // 8 warp totals

    const int c0 = blk << 10;
#pragma unroll
    for (int q = 0; q < 4; q++) {
        int r = t * 4 + q;
        s_ad[r] = (c0 + r < n) ? g_ad[c0 + r] : -1;
    }
    __syncthreads();
    if (wid == 0 && lane < 8) {
        int w = s_w[lane];
#pragma unroll
        for (int o = 1; o < 8; o <<= 1) {
            int u = __shfl_up_sync(0x000000ffu, w, o);
            if (lane >= o) w += u;
        }
        s_w[lane] = w;
    }
    __syncthreads();
    const int base = (wid ? s_w[wid - 1] : 0) + (inc - run);

    if (blk == 0) {
#pragma unroll
        for (int q = 0; q < 32; q++) g_boff[t * 32 + q] = base + v[q];
    }

    int p0 = base + v[0 * NCHUNK + blk];
    int p1 = base + v[1 * NCHUNK + blk];
    int p2 = base + v[2 * NCHUNK + blk];
    int p3 = base + v[3 * NCHUNK + blk];
    for (int r = 0; r < 1024; r++) {
        int a = s_ad[r];
        if (a >= 0 && (a >> 2) == t) {
            int q = a & 3;
            int pos = (q == 0) ? p0++ : (q == 1) ? p1++ : (q == 2) ? p2++ : p3++;
            g_bucket[pos] = c0 + r;
        }
    }
}

// ---------------------------------------------------------------------------
// Flash kernel (R12 static config): blocks [0, nFlash) = 64 rowtiles x
// 4 col-quarters (2 CTA/SM); blocks [nFlash, nFlash+8) run the scatter path.
// Block tile 128x128 sim, K=128 bf16, double-buffered B tiles.
// Epilogue: z = fma(2^t, w, z) — 1 EX2 + 1 FFMA per element (w in {1,0}).
// ---------------------------------------------------------------------------
__global__ __launch_bounds__(256, 2)
void flash_kernel(int n, int nFlash) {
    extern __shared__ char smem[];
    if ((int)blockIdx.x >= nFlash) {
        scatter_body(smem, n, (int)blockIdx.x - nFlash);
        return;
    }
    const uint32_t sbase = smem_u32(smem);
    const int tid  = threadIdx.x;
    const int wid  = tid >> 5;
    const int lane = tid & 31;
    const int warpRow = (wid & 3) * 32;
    const int warpCol = (wid >> 2) * 64;

    const int rt    = (int)blockIdx.x >> 2;
    const int quart = (int)blockIdx.x & 3;
    const int row0  = rt * 128;
    const int col0b = quart * (n >> 2);
    const int NT    = (n >> 2) >> 7;        // 16 col tiles of 128

    {
#pragma unroll
        for (int i = 0; i < 8; i++) {
            int v = tid + 256 * i;
            int ch = v >> 10, w = v & 1023;
            int r = w >> 3, g8 = w & 7;
            cp_async16(sbase + SM_A + ch * 16384 + swz((uint32_t)(r * 128 + g8 * 16)),
                       &g_Ah[(size_t)(row0 + r) * 128 + ch * 64 + g8 * 8]);
        }
#pragma unroll
        for (int i = 0; i < 8; i++) {
            int v = tid + 256 * i;
            int ch = v >> 10, w = v & 1023;
            int r = w >> 3, g8 = w & 7;
            cp_async16(sbase + SM_B + ch * 16384 + swz((uint32_t)(r * 128 + g8 * 16)),
                       &g_Bh[(size_t)(col0b + r) * 128 + ch * 64 + g8 * 8]);
        }
        if (tid < 32)
            cp_async16(sbase + SM_MASK + tid * 16, &g_w[col0b + tid * 4]);
        CP_COMMIT();
    }

    const uint32_t aRow = (uint32_t)(warpRow + (lane & 15)) * 128u;
    const uint32_t aXor = (uint32_t)((lane & 15) & 7) << 4;
    const uint32_t aKl  = (uint32_t)(lane >> 4) * 16u;
    const int      jB   = (lane & 7) + ((lane >> 4) << 3);
    const uint32_t bRow = (uint32_t)(warpCol + jB) * 128u;
    const uint32_t bXor = (uint32_t)(lane & 7) << 4;
    const uint32_t bKl  = (uint32_t)((lane >> 3) & 1) * 16u;

    float acc[2][8][4];
#pragma unroll
    for (int mt = 0; mt < 2; mt++)
#pragma unroll
        for (int nt = 0; nt < 8; nt++)
#pragma unroll
            for (int e = 0; e < 4; e++) acc[mt][nt][e] = 0.0f;

    float zrun[4] = {0.0f, 0.0f, 0.0f, 0.0f};

    for (int t = 0; t < NT; t++) {
        const int buf = t & 1;
        CP_WAIT0();
        __syncthreads();

        if (t + 1 < NT) {
            int j0 = col0b + (t + 1) * 128;
            uint32_t sb = sbase + SM_B + (buf ^ 1) * 32768;
#pragma unroll
            for (int i = 0; i < 8; i++) {
                int v = tid + 256 * i;
                int ch = v >> 10, w = v & 1023;
                int r = w >> 3, g8 = w & 7;
                cp_async16(sb + ch * 16384 + swz((uint32_t)(r * 128 + g8 * 16)),
                           &g_Bh[(size_t)(j0 + r) * 128 + ch * 64 + g8 * 8]);
            }
            if (tid < 32)
                cp_async16(sbase + SM_MASK + (buf ^ 1) * 512 + tid * 16,
                           &g_w[j0 + tid * 4]);
        }
        CP_COMMIT();

        const uint32_t bBB = sbase + SM_B + (uint32_t)buf * 32768u;
#pragma unroll
        for (int ks = 0; ks < 8; ks++) {
            const uint32_t ch = (uint32_t)(ks >> 2);
            const uint32_t kk = (uint32_t)(ks & 3) * 32u;
            const uint32_t kOffA = (kk + aKl) ^ aXor;
            const uint32_t kOffB = (kk + bKl) ^ bXor;
            uint32_t a0[4], a1[4];
            const uint32_t aCB = sbase + SM_A + ch * 16384u;
            ldsm4(a0[0], a0[1], a0[2], a0[3], aCB + aRow + kOffA);
            ldsm4(a1[0], a1[1], a1[2], a1[3], aCB + 2048u + aRow + kOffA);
            uint32_t b[8][2];
            const uint32_t bCB = bBB + ch * 16384u;
#pragma unroll
            for (int p = 0; p < 4; p++)
                ldsm4(b[2 * p][0], b[2 * p][1], b[2 * p + 1][0], b[2 * p + 1][1],
                      bCB + bRow + (uint32_t)p * 2048u + kOffB);
#pragma unroll
            for (int nt = 0; nt < 8; nt++) {
                mma16816(acc[0][nt], a0, b[nt]);
                mma16816(acc[1][nt], a1, b[nt]);
            }
        }

        {
            const float* mk = (const float*)(smem + SM_MASK + buf * 512)
                              + warpCol + (lane & 3) * 2;
#pragma unroll
            for (int mt = 0; mt < 2; mt++)
#pragma unroll
                for (int rp = 0; rp < 2; rp++) {
                    float zs = 0.0f;
#pragma unroll
                    for (int nt = 0; nt < 8; nt++) {
                        float2 mv = *(const float2*)(mk + nt * 8);
                        zs = fmaf(fexp2(acc[mt][nt][rp * 2 + 0]), mv.x, zs);
                        zs = fmaf(fexp2(acc[mt][nt][rp * 2 + 1]), mv.y, zs);
                    }
                    zrun[mt * 2 + rp] += zs;
                }
#pragma unroll
            for (int mt = 0; mt < 2; mt++)
#pragma unroll
                for (int nt = 0; nt < 8; nt++)
#pragma unroll
                    for (int e = 0; e < 4; e++) acc[mt][nt][e] = 0.0f;
        }
    }

#pragma unroll
    for (int s = 0; s < 4; s++) {
        float z = zrun[s];
        z += __shfl_xor_sync(0xffffffffu, z, 1);
        z += __shfl_xor_sync(0xffffffffu, z, 2);
        if ((lane & 3) == 0) {
            int mt = s >> 1, rp = s & 1;
            int row = row0 + warpRow + mt * 16 + rp * 8 + (lane >> 2);
            int slot = quart * 2 + (wid >> 2);
            g_pz[slot * NMAX + row] = z;
        }
    }
}

// ---------------------------------------------------------------------------
// matched: one warp per row; lane = one float4 of the dot; bucket loop with
// software-pipelined b-row loads and parallel 8-lane z-slot sum. Block 0
// re-zeroes g_cnt for the next graph replay. Row losses accumulate into a
// fixed-point u64 (order-independent -> deterministic); last block writes
// the mean. lz = log2(z) directly (no offset in this formulation).
// ---------------------------------------------------------------------------
__global__ __launch_bounds__(256)
void matched_kernel(const float* __restrict__ logits,
                    const float* __restrict__ labels,
                    float* __restrict__ out, int n, int nblocks) {
    if (blockIdx.x == 0) {
        for (int i = threadIdx.x; i < 8192; i += 256) g_cnt[i] = 0;
    }

    const int warp = threadIdx.x >> 5;
    const int lane = threadIdx.x & 31;
    const int row  = blockIdx.x * 8 + warp;

    if (row < n) {                     // warp-uniform
        const int id = g_ad[row];
        if (id >= 0) {                 // warp-uniform
            // 8 lanes load the 8 z-slots in parallel, 3-shuffle sum
            float zp = (lane < 8) ? g_pz[lane * NMAX + row] : 0.0f;
            zp += __shfl_xor_sync(0xffffffffu, zp, 1);
            zp += __shfl_xor_sync(0xffffffffu, zp, 2);
            zp += __shfl_xor_sync(0xffffffffu, zp, 4);
            const float lz = flog2(__shfl_sync(0xffffffffu, zp, 0));

            const float4 a4 = reinterpret_cast<const float4*>(logits + (size_t)row * DDIM)[lane];
            const int s = g_boff[id * NCHUNK];
            const int e = g_boff[(id + 1) * NCHUNK];

            // software pipeline: b row for entry p+1 loads during reduce of p
            float acc = 0.0f;
            int j = g_bucket[s];       // bucket non-empty: contains `row` itself
            float4 b = reinterpret_cast<const float4*>(labels + (size_t)j * DDIM)[lane];
            for (int p = s; p < e; p++) {     // uniform across warp
                const float4 bc = b;
                if (p + 1 < e) {              // warp-uniform branch
                    const int j2 = g_bucket[p + 1];
                    b = reinterpret_cast<const float4*>(labels + (size_t)j2 * DDIM)[lane];
                }
                float d = a4.x * bc.x + a4.y * bc.y + a4.z * bc.z + a4.w * bc.w;
#pragma unroll
                for (int o = 16; o; o >>= 1) d += __shfl_xor_sync(0xffffffffu, d, o);
                acc += fminf(lz - d * LOG2E, CAPV);
            }
            if (lane == 0 && acc != 0.0f)
                atomicAdd(&g_fx, (unsigned long long)llrintf(acc * FXSCALE));
        }
    }

    // finalize: last block to arrive writes the mean
    __syncthreads();
    if (threadIdx.x == 0) {
        __threadfence();
        unsigned t = atomicAdd(&g_done, 1u);
        if (t == (unsigned)(nblocks - 1)) {
            unsigned long long fx = atomicAdd(&g_fx, 0ULL);
            out[0] = (float)((double)fx / (double)FXSCALE / (double)n);
        }
    }
}

// ---------------------------------------------------------------------------
extern "C" void kernel_launch(void* const* d_in, const int* in_sizes, int n_in,
                              void* d_out, int out_size) {
    const float* logits = (const float*)d_in[0];
    const float* labels = (const float*)d_in[1];
    const int*   pad    = (const int*)d_in[2];
    const void*  ad     = d_in[3];
    float*       out    = (float*)d_out;
    const int n = in_sizes[2];           // B*S = 8192

    // g_cnt is zeroed at module load and re-zeroed by matched_kernel each call.
    prep_all_kernel<<<(n * DDIM / 4 + 255) / 256, 256>>>(logits, labels, pad, ad, n);

    const int nFlash = (n / 128) * 4;    // 256
    cudaFuncSetAttribute(flash_kernel,
                         cudaFuncAttributeMaxDynamicSharedMemorySize, SM_TOTAL);
    flash_kernel<<<nFlash + NCHUNK, 256, SM_TOTAL>>>(n, nFlash);

    const int nblocks = (n + 7) / 8;
    matched_kernel<<<nblocks, 256>>>(logits, labels, out, n, nblocks);
}